// round 9
// baseline (speedup 1.0000x reference)
#include <cuda_runtime.h>

// ---------------------------------------------------------------------------
// MWDLSTMGCT: only the low-pass wavelet chain + LSTM-3 affect the output.
//   xl1 = avgpool2(sigmoid(x @ W1L^T + b1L))        (256 x 512)
//   xl2 = avgpool2(sigmoid(xl1 @ W2L^T + b2L))      (256 x 256)
//   h   = LSTM(xl2 as scalar sequence; Wih3,Whh3,b3), final hidden (256 x 100)
//   out = h @ Wout^T + bout                          (256 x 1)
// ---------------------------------------------------------------------------

#define NBATCH 256
#define HID    100
#define GATES  400   // 4*HID
#define TSTEPS 256

__device__ __align__(16) float g_xl1[256 * 512];
__device__ __align__(16) float g_xl2[256 * 256];

__device__ __forceinline__ float sigf(float x) { return 1.f / (1.f + __expf(-x)); }
// tanh(x) = 1 - 2/(exp(2x)+1); exact saturation, 1 MUFU + few ALU.
__device__ __forceinline__ float tanh_fast(float x) {
    return 1.f - 2.f / (__expf(2.f * x) + 1.f);
}

// ---------------------------------------------------------------------------
// Fused GEMM (C = A @ W^T), bias, sigmoid, avgpool2 along N.
// Tile 32(M) x 64(N), K-slices of 16, double-buffered smem, 256 threads.
// Microtile 4x2: ty=tid>>5 (0..7) -> rows 4ty..4ty+3, tx=tid&31 -> cols
// 2tx..2tx+1. A-read is a warp-uniform float4 broadcast, B-read LDS.64
// conflict-free. Grid (N/64, M/32) -> 128 CTAs for gemm1 (full chip).
// A: [256][K], W: [N][K], out: [256][N/2]
// ---------------------------------------------------------------------------
template <int K>
__device__ __forceinline__ void gemm_sig_pool_body(
    const float* __restrict__ A, const float* __restrict__ W,
    const float* __restrict__ bias, float* __restrict__ out, int halfN)
{
    __shared__ __align__(16) float As[2][16][32];
    __shared__ __align__(16) float Bs[2][16][64];

    const int m0 = blockIdx.y * 32;
    const int n0 = blockIdx.x * 64;
    const int tid = threadIdx.x;

    // B loaders: all 256 threads, one float4 each per K-slice.
    const int lmB = tid >> 2;            // 0..63
    const int lkB = (tid & 3) * 4;       // 0,4,8,12
    const float* Bg = W + (n0 + lmB) * K + lkB;
    // A loaders: threads 0..127, one float4 each per K-slice.
    const bool hasA = tid < 128;
    const int lmA = (tid & 127) >> 2;    // 0..31
    const int lkA = (tid & 3) * 4;
    const float* Ag = A + (m0 + lmA) * K + lkA;

    float4 b4 = *(const float4*)(Bg);
    float4 a4 = hasA ? *(const float4*)(Ag) : make_float4(0.f, 0.f, 0.f, 0.f);
    Bs[0][lkB + 0][lmB] = b4.x; Bs[0][lkB + 1][lmB] = b4.y;
    Bs[0][lkB + 2][lmB] = b4.z; Bs[0][lkB + 3][lmB] = b4.w;
    if (hasA) {
        As[0][lkA + 0][lmA] = a4.x; As[0][lkA + 1][lmA] = a4.y;
        As[0][lkA + 2][lmA] = a4.z; As[0][lkA + 3][lmA] = a4.w;
    }
    __syncthreads();

    const int tx = tid & 31;   // 0..31 -> 2 N-cols
    const int ty = tid >> 5;   // 0..7  -> 4 M-rows

    float acc[4][2] = {};
    const int NT = K / 16;

    for (int tI = 0; tI < NT; tI++) {
        const int cur = tI & 1;
        if (tI + 1 < NT) {
            b4 = *(const float4*)(Bg + (tI + 1) * 16);
            if (hasA) a4 = *(const float4*)(Ag + (tI + 1) * 16);
        }
        #pragma unroll
        for (int kk = 0; kk < 16; kk++) {
            float4 av = *(const float4*)&As[cur][kk][ty * 4];
            float2 bv = *(const float2*)&Bs[cur][kk][tx * 2];
            acc[0][0] = fmaf(av.x, bv.x, acc[0][0]);
            acc[0][1] = fmaf(av.x, bv.y, acc[0][1]);
            acc[1][0] = fmaf(av.y, bv.x, acc[1][0]);
            acc[1][1] = fmaf(av.y, bv.y, acc[1][1]);
            acc[2][0] = fmaf(av.z, bv.x, acc[2][0]);
            acc[2][1] = fmaf(av.z, bv.y, acc[2][1]);
            acc[3][0] = fmaf(av.w, bv.x, acc[3][0]);
            acc[3][1] = fmaf(av.w, bv.y, acc[3][1]);
        }
        if (tI + 1 < NT) {
            const int nb = cur ^ 1;
            Bs[nb][lkB + 0][lmB] = b4.x; Bs[nb][lkB + 1][lmB] = b4.y;
            Bs[nb][lkB + 2][lmB] = b4.z; Bs[nb][lkB + 3][lmB] = b4.w;
            if (hasA) {
                As[nb][lkA + 0][lmA] = a4.x; As[nb][lkA + 1][lmA] = a4.y;
                As[nb][lkA + 2][lmA] = a4.z; As[nb][lkA + 3][lmA] = a4.w;
            }
        }
        __syncthreads();
    }

    const float bn0 = bias[n0 + tx * 2 + 0];
    const float bn1 = bias[n0 + tx * 2 + 1];
    const int ocol = (n0 >> 1) + tx;
    #pragma unroll
    for (int i = 0; i < 4; i++) {
        const int m = m0 + ty * 4 + i;
        float s0 = sigf(acc[i][0] + bn0);
        float s1 = sigf(acc[i][1] + bn1);
        out[m * halfN + ocol] = 0.5f * (s0 + s1);
    }
}

__global__ void __launch_bounds__(256) gemm1_kernel(
    const float* __restrict__ A, const float* __restrict__ W,
    const float* __restrict__ bias)
{
    gemm_sig_pool_body<1024>(A, W, bias, g_xl1, 512);
}

__global__ void __launch_bounds__(256) gemm2_kernel(
    const float* __restrict__ W, const float* __restrict__ bias)
{
    gemm_sig_pool_body<512>(g_xl1, W, bias, g_xl2, 256);
}

// ---------------------------------------------------------------------------
// LSTM-3, persistent per-CTA, 2 batch rows per CTA, row-staggered pipeline.
// 512 threads:
//   t in [0,400)    : gate threads; Whh row t in registers. Phase p computes
//                     z for row (p&1), step (p>>1), reading h{row}_s.
//   t in [416,512)  : 96 epilogue threads (whole warps 13..15, disjoint from
//                     gate warps -> no divergence). Phase p applies the gate
//                     nonlinearity to the PREVIOUS phase's z (row (p-1)&1),
//                     overlapping the MUFU chain with the gate GEMV.
//                     Thread j=t-416 owns hidden unit j (and j<4 also 96+j),
//                     with per-row cell state in registers.
// One barrier per phase, 2 phases per step + 1 tail phase.
// ---------------------------------------------------------------------------
struct EpiState { float c0, c1; };

__device__ __forceinline__ void epi_unit(int row, int j,
                                         float (*z_s)[GATES],
                                         float* __restrict__ h0_s,
                                         float* __restrict__ h1_s,
                                         EpiState& st)
{
    float iz = z_s[row][j];
    float fz = z_s[row][HID + j];
    float gz = z_s[row][2 * HID + j];
    float oz = z_s[row][3 * HID + j];
    float c = row ? st.c1 : st.c0;
    c = sigf(fz) * c + sigf(iz) * tanh_fast(gz);
    float h = sigf(oz) * tanh_fast(c);
    if (row) { st.c1 = c; h1_s[j] = h; }
    else     { st.c0 = c; h0_s[j] = h; }
}

__global__ void __launch_bounds__(512, 1) lstm_kernel(
    const float* __restrict__ Wih, const float* __restrict__ Whh,
    const float* __restrict__ b3,  const float* __restrict__ Wout,
    const float* __restrict__ bout, float* __restrict__ out)
{
    const int r0 = blockIdx.x * 2;
    const int t = threadIdx.x;

    __shared__ __align__(16) float h0_s[HID];
    __shared__ __align__(16) float h1_s[HID];
    __shared__ float z_s[2][GATES];
    __shared__ float x_s[2][TSTEPS];
    __shared__ float red0[HID], red1[HID];

    float wreg[HID];
    float wih_g = 0.f, bg = 0.f;
    if (t < GATES) {
        const float* wrow = Whh + t * HID;
        #pragma unroll
        for (int k = 0; k < HID; k += 4) {
            float4 w4 = *(const float4*)(wrow + k);
            wreg[k] = w4.x; wreg[k + 1] = w4.y;
            wreg[k + 2] = w4.z; wreg[k + 3] = w4.w;
        }
        wih_g = Wih[t];
        bg = b3[t];
    }
    if (t < TSTEPS) {
        x_s[0][t] = g_xl2[r0 * TSTEPS + t];
        x_s[1][t] = g_xl2[(r0 + 1) * TSTEPS + t];
    }
    if (t < HID) { h0_s[t] = 0.f; h1_s[t] = 0.f; }

    const bool isEpi = (t >= 416);
    const int j = t - 416;                 // 0..95
    const bool hasB = isEpi && (j < HID - 96);  // units 96..99
    EpiState stA = {0.f, 0.f}, stB = {0.f, 0.f};
    __syncthreads();

    #pragma unroll 2
    for (int p = 0; p < 2 * TSTEPS; p++) {
        const int row = p & 1;
        if (t < GATES) {
            const float* hs = row ? h1_s : h0_s;
            float za = fmaf(wih_g, x_s[row][p >> 1], bg);
            float zb = 0.f;
            const float2* h2 = (const float2*)hs;
            #pragma unroll
            for (int k = 0; k < HID / 2; k++) {
                float2 h = h2[k];
                za = fmaf(wreg[2 * k],     h.x, za);
                zb = fmaf(wreg[2 * k + 1], h.y, zb);
            }
            z_s[row][t] = za + zb;
        } else if (isEpi && p > 0) {
            const int prow = row ^ 1;      // row of phase p-1
            epi_unit(prow, j, z_s, h0_s, h1_s, stA);
            if (hasB) epi_unit(prow, 96 + j, z_s, h0_s, h1_s, stB);
        }
        __syncthreads();
    }
    // Tail: nonlinearity for the last phase's z (row 1, step 255).
    if (isEpi) {
        epi_unit(1, j, z_s, h0_s, h1_s, stA);
        if (hasB) epi_unit(1, 96 + j, z_s, h0_s, h1_s, stB);
    }
    __syncthreads();

    // Final projection: out[r] = h_final . Wout + bout
    if (t < HID) {
        float w = Wout[t];
        red0[t] = h0_s[t] * w;
        red1[t] = h1_s[t] * w;
    }
    __syncthreads();
    if (t == 0) {
        float s = bout[0];
        for (int k = 0; k < HID; k++) s += red0[k];
        out[r0] = s;
    }
    if (t == 1) {
        float s = bout[0];
        for (int k = 0; k < HID; k++) s += red1[k];
        out[r0 + 1] = s;
    }
}

// ---------------------------------------------------------------------------
// Launch. Input order (metadata.txt): x, W1H, b1H, W1L, b1L, W2H, b2H, W2L,
// b2L, Wih1, Whh1, b1, Wih2, Whh2, b2, Wih3, Whh3, b3, Wout, bout.
// Only the low-pass + LSTM-3 inputs are used.
// ---------------------------------------------------------------------------
extern "C" void kernel_launch(void* const* d_in, const int* in_sizes, int n_in,
                              void* d_out, int out_size)
{
    const float* x    = (const float*)d_in[0];
    const float* W1L  = (const float*)d_in[3];
    const float* b1L  = (const float*)d_in[4];
    const float* W2L  = (const float*)d_in[7];
    const float* b2L  = (const float*)d_in[8];
    const float* Wih3 = (const float*)d_in[15];
    const float* Whh3 = (const float*)d_in[16];
    const float* b3   = (const float*)d_in[17];
    const float* Wout = (const float*)d_in[18];
    const float* bout = (const float*)d_in[19];
    float* out = (float*)d_out;

    dim3 grid1(16, 8);   // N=1024/64, M=256/32 -> 128 CTAs
    dim3 grid2(8, 8);    // N=512/64,  M=256/32 -> 64 CTAs
    gemm1_kernel<<<grid1, 256>>>(x, W1L, b1L);
    gemm2_kernel<<<grid2, 256>>>(W2L, b2L);
    lstm_kernel<<<128, 512>>>(Wih3, Whh3, b3, Wout, bout, out);
}

// round 10
// speedup vs baseline: 1.1992x; 1.1992x over previous
#include <cuda_runtime.h>

// ---------------------------------------------------------------------------
// MWDLSTMGCT: only the low-pass wavelet chain + LSTM-3 affect the output.
//   xl1 = avgpool2(sigmoid(x @ W1L^T + b1L))        (256 x 512)
//   xl2 = avgpool2(sigmoid(xl1 @ W2L^T + b2L))      (256 x 256)
//   h   = LSTM(xl2 as scalar sequence; Wih3,Whh3,b3), final hidden (256 x 100)
//   out = h @ Wout^T + bout                          (256 x 1)
// ---------------------------------------------------------------------------

#define NBATCH 256
#define HID    100
#define GATES  400   // 4*HID
#define TSTEPS 256

__device__ __align__(16) float g_xl1[256 * 512];
__device__ __align__(16) float g_xl2[256 * 256];

__device__ __forceinline__ float sigf(float x) { return 1.f / (1.f + __expf(-x)); }
// tanh(x) = 1 - 2/(exp(2x)+1); exact saturation.
__device__ __forceinline__ float tanh_fast(float x) {
    return 1.f - 2.f / (__expf(2.f * x) + 1.f);
}

// ---------------------------------------------------------------------------
// Fused GEMM (C = A @ W^T), bias, sigmoid, avgpool2 along N.
// Tile 32(M) x 64(N), K-slices of 16, TRIPLE-buffered smem with a depth-3
// LDG pipeline: the STS for slice t+1 uses a register loaded 2 iterations
// earlier (~2 compute-slices of DRAM latency in flight). 256 threads,
// microtile 4x2. Grid (N/64, M/32).
// A: [256][K], W: [N][K], out: [256][N/2]
// ---------------------------------------------------------------------------
template <int K>
__device__ __forceinline__ void gemm_sig_pool_body(
    const float* __restrict__ A, const float* __restrict__ W,
    const float* __restrict__ bias, float* __restrict__ out, int halfN)
{
    __shared__ __align__(16) float As[3][16][32];
    __shared__ __align__(16) float Bs[3][16][64];

    const int m0 = blockIdx.y * 32;
    const int n0 = blockIdx.x * 64;
    const int tid = threadIdx.x;

    const int lmB = tid >> 2;            // 0..63
    const int lkB = (tid & 3) * 4;       // 0,4,8,12
    const float* Bg = W + (n0 + lmB) * K + lkB;
    const bool hasA = tid < 128;
    const int lmA = (tid & 127) >> 2;    // 0..31
    const int lkA = (tid & 3) * 4;
    const float* Ag = A + (m0 + lmA) * K + lkA;

    const int tx = tid & 31;   // 2 N-cols
    const int ty = tid >> 5;   // 4 M-rows

    float acc[4][2] = {};
    const int NT = K / 16;

    auto ldA = [&](int s) -> float4 {
        return hasA ? *(const float4*)(Ag + s * 16) : make_float4(0.f, 0.f, 0.f, 0.f);
    };
    auto ldB = [&](int s) -> float4 { return *(const float4*)(Bg + s * 16); };
    auto stsA = [&](int buf, float4 v) {
        if (hasA) {
            As[buf][lkA + 0][lmA] = v.x; As[buf][lkA + 1][lmA] = v.y;
            As[buf][lkA + 2][lmA] = v.z; As[buf][lkA + 3][lmA] = v.w;
        }
    };
    auto stsB = [&](int buf, float4 v) {
        Bs[buf][lkB + 0][lmB] = v.x; Bs[buf][lkB + 1][lmB] = v.y;
        Bs[buf][lkB + 2][lmB] = v.z; Bs[buf][lkB + 3][lmB] = v.w;
    };
    auto compute = [&](int buf) {
        #pragma unroll
        for (int kk = 0; kk < 16; kk++) {
            float4 av = *(const float4*)&As[buf][kk][ty * 4];
            float2 bv = *(const float2*)&Bs[buf][kk][tx * 2];
            acc[0][0] = fmaf(av.x, bv.x, acc[0][0]);
            acc[0][1] = fmaf(av.x, bv.y, acc[0][1]);
            acc[1][0] = fmaf(av.y, bv.x, acc[1][0]);
            acc[1][1] = fmaf(av.y, bv.y, acc[1][1]);
            acc[2][0] = fmaf(av.z, bv.x, acc[2][0]);
            acc[2][1] = fmaf(av.z, bv.y, acc[2][1]);
            acc[3][0] = fmaf(av.w, bv.x, acc[3][0]);
            acc[3][1] = fmaf(av.w, bv.y, acc[3][1]);
        }
    };

    // Preload 3 slices into registers; stage slice 0 into buffer 0.
    float4 a0 = ldA(0), b0 = ldB(0);
    float4 a1 = ldA(1), b1 = ldB(1);
    float4 a2 = ldA(2), b2 = ldB(2);
    stsA(0, a0); stsB(0, b0);
    __syncthreads();

    // Hand-unrolled stride-3 pipeline: at iter tI (buf = tI%3):
    //   compute(buf); LDG reg[tI%3] <- slice tI+3; STS buf[(tI+1)%3] <- reg[(tI+1)%3]
    for (int i = 0; i < NT; i += 3) {
        {   // tI = i, buf 0
            compute(0);
            if (i + 3 < NT) { a0 = ldA(i + 3); b0 = ldB(i + 3); }
            if (i + 1 < NT) { stsA(1, a1); stsB(1, b1); }
            __syncthreads();
        }
        if (i + 1 < NT) {   // tI = i+1, buf 1
            compute(1);
            if (i + 4 < NT) { a1 = ldA(i + 4); b1 = ldB(i + 4); }
            if (i + 2 < NT) { stsA(2, a2); stsB(2, b2); }
            __syncthreads();
        }
        if (i + 2 < NT) {   // tI = i+2, buf 2
            compute(2);
            if (i + 5 < NT) { a2 = ldA(i + 5); b2 = ldB(i + 5); }
            if (i + 3 < NT) { stsA(0, a0); stsB(0, b0); }
            __syncthreads();
        }
    }

    const float bn0 = bias[n0 + tx * 2 + 0];
    const float bn1 = bias[n0 + tx * 2 + 1];
    const int ocol = (n0 >> 1) + tx;
    #pragma unroll
    for (int i = 0; i < 4; i++) {
        const int m = m0 + ty * 4 + i;
        float s0 = sigf(acc[i][0] + bn0);
        float s1 = sigf(acc[i][1] + bn1);
        out[m * halfN + ocol] = 0.5f * (s0 + s1);
    }
}

__global__ void __launch_bounds__(256) gemm1_kernel(
    const float* __restrict__ A, const float* __restrict__ W,
    const float* __restrict__ bias)
{
    gemm_sig_pool_body<1024>(A, W, bias, g_xl1, 512);
}

__global__ void __launch_bounds__(256) gemm2_kernel(
    const float* __restrict__ W, const float* __restrict__ bias)
{
    gemm_sig_pool_body<512>(g_xl1, W, bias, g_xl2, 256);
}

// ---------------------------------------------------------------------------
// LSTM-3, persistent per-CTA, 2 batch rows per CTA, SPLIT-K gate GEMV.
// 832 threads (26 warps, 78-reg cap):
//   t in [0,400)   : half-A of gate t, k in [0,50), 50 weights in regs,
//                    plus the wih*x + b term.
//   t in [400,800) : half-B of gate t-400, k in [50,100), wih=b=0 so the
//                    instruction sequence is IDENTICAL (no divergence; the
//                    z-store target is a data-dependent pointer).
//   25 gate warps (~6/SMSP) hide LDS + FFMA-chain latency; FMA floor
//   ~1250 cyc/step.
// Epilogue: threads 0..199, one (row, hidden-unit) each; z = zA + zB.
// ---------------------------------------------------------------------------
__global__ void __launch_bounds__(832, 1) lstm_kernel(
    const float* __restrict__ Wih, const float* __restrict__ Whh,
    const float* __restrict__ b3,  const float* __restrict__ Wout,
    const float* __restrict__ bout, float* __restrict__ out)
{
    const int r0 = blockIdx.x * 2;
    const int t = threadIdx.x;

    __shared__ __align__(8) float2 h_s[HID];
    __shared__ float zA[2][GATES];
    __shared__ float zB[2][GATES];
    __shared__ float x_s[2][TSTEPS];
    __shared__ float red0[HID], red1[HID];

    const bool isGate = t < 800;
    const bool halfA = t < 400;
    const int g = halfA ? t : t - 400;
    const int kb = halfA ? 0 : 50;

    float wreg[50];
    float wih_g = 0.f, bg = 0.f;
    float* zdst0 = &zA[0][0];
    float* zdst1 = &zA[1][0];
    if (isGate) {
        const float* wrow = Whh + g * HID + kb;
        #pragma unroll
        for (int k = 0; k < 50; k += 2) {
            float2 w = *(const float2*)(wrow + k);
            wreg[k] = w.x; wreg[k + 1] = w.y;
        }
        if (halfA) { wih_g = Wih[g]; bg = b3[g]; }
        zdst0 = halfA ? &zA[0][g] : &zB[0][g];
        zdst1 = halfA ? &zA[1][g] : &zB[1][g];
    }
    if (t < TSTEPS) {
        x_s[0][t] = g_xl2[r0 * TSTEPS + t];
        x_s[1][t] = g_xl2[(r0 + 1) * TSTEPS + t];
    }
    if (t < HID) h_s[t] = make_float2(0.f, 0.f);
    float c_st = 0.f;   // t<100: row0 unit t; 100..199: row1 unit t-100
    __syncthreads();

    for (int step = 0; step < TSTEPS; step++) {
        if (isGate) {
            float z0 = fmaf(wih_g, x_s[0][step], bg);
            float z1 = fmaf(wih_g, x_s[1][step], bg);
            const float2* hp = &h_s[kb];
            #pragma unroll
            for (int k = 0; k < 50; k++) {
                float2 h = hp[k];
                z0 = fmaf(wreg[k], h.x, z0);
                z1 = fmaf(wreg[k], h.y, z1);
            }
            *zdst0 = z0;
            *zdst1 = z1;
        }
        __syncthreads();
        if (t < 2 * HID) {
            const int row = (t >= HID) ? 1 : 0;
            const int j = t - row * HID;
            float iz = zA[row][j]           + zB[row][j];
            float fz = zA[row][HID + j]     + zB[row][HID + j];
            float gz = zA[row][2 * HID + j] + zB[row][2 * HID + j];
            float oz = zA[row][3 * HID + j] + zB[row][3 * HID + j];
            c_st = sigf(fz) * c_st + sigf(iz) * tanh_fast(gz);
            float h = sigf(oz) * tanh_fast(c_st);
            ((float*)&h_s[j])[row] = h;
        }
        __syncthreads();
    }

    // Final projection: out[r] = h_final . Wout + bout
    if (t < HID) {
        float w = Wout[t];
        red0[t] = h_s[t].x * w;
        red1[t] = h_s[t].y * w;
    }
    __syncthreads();
    if (t == 0) {
        float s = bout[0];
        for (int k = 0; k < HID; k++) s += red0[k];
        out[r0] = s;
    }
    if (t == 1) {
        float s = bout[0];
        for (int k = 0; k < HID; k++) s += red1[k];
        out[r0 + 1] = s;
    }
}

// ---------------------------------------------------------------------------
// Launch. Input order (metadata.txt): x, W1H, b1H, W1L, b1L, W2H, b2H, W2L,
// b2L, Wih1, Whh1, b1, Wih2, Whh2, b2, Wih3, Whh3, b3, Wout, bout.
// Only the low-pass + LSTM-3 inputs are used.
// ---------------------------------------------------------------------------
extern "C" void kernel_launch(void* const* d_in, const int* in_sizes, int n_in,
                              void* d_out, int out_size)
{
    const float* x    = (const float*)d_in[0];
    const float* W1L  = (const float*)d_in[3];
    const float* b1L  = (const float*)d_in[4];
    const float* W2L  = (const float*)d_in[7];
    const float* b2L  = (const float*)d_in[8];
    const float* Wih3 = (const float*)d_in[15];
    const float* Whh3 = (const float*)d_in[16];
    const float* b3   = (const float*)d_in[17];
    const float* Wout = (const float*)d_in[18];
    const float* bout = (const float*)d_in[19];
    float* out = (float*)d_out;

    dim3 grid1(16, 8);   // N=1024/64, M=256/32 -> 128 CTAs
    dim3 grid2(8, 8);    // N=512/64,  M=256/32 -> 64 CTAs
    gemm1_kernel<<<grid1, 256>>>(x, W1L, b1L);
    gemm2_kernel<<<grid2, 256>>>(W2L, b2L);
    lstm_kernel<<<128, 832>>>(Wih3, Whh3, b3, Wout, bout, out);
}